// round 12
// baseline (speedup 1.0000x reference)
#include <cuda_runtime.h>

// Problem constants
#define NG 2048   // G
#define NC 16     // C
#define NM 16     // m
// exp(x/gamma) = ex2(x * 100 * log2(e));  gamma*ln(s) = lg2(s) * gamma*ln2
#define KEXP 144.2695040889f
#define KLOG 0.00693147180560f

#define NPAIR (NC * NG / 2)      // 16384 (c,g) item-pairs in kA
#define KA_BLK 592               // 148 SMs * 4 blocks -> exactly one wave
#define KA_NW  (KA_BLK * 8)      // 4736 warps

typedef unsigned long long u64;

// Packed layouts: element [g*16 + j] = (val[b=2j], val[b=2j+1])
__device__ u64 g_Rt2[NG * 16];        // R (un-normalized; scale in g_max)
__device__ u64 g_Cv2[NC * NG * 16];   // Cv_pre
__device__ u64 g_Hs2[NG * 16];        // Hs_pre
__device__ int g_max[16][8];          // banked float-bit maxes (values >= 0)
// slots: iter i uses 3i (Cv), 3i+1 (Hs), 3i+2 (R). Zero at module load =>
// scale 1.0; replay-idempotent (each replay atomicMax-es identical values).

// ---- f32x2 helpers (sm_103a packed fp32) ----
__device__ __forceinline__ u64 pk(float x, float y) {
    u64 v; asm("mov.b64 %0, {%1,%2};" : "=l"(v) : "f"(x), "f"(y)); return v;
}
__device__ __forceinline__ float2 unpk(u64 v) {
    float2 r; asm("mov.b64 {%0,%1}, %2;" : "=f"(r.x), "=f"(r.y) : "l"(v)); return r;
}
__device__ __forceinline__ u64 mul2(u64 a, u64 b) {
    u64 c; asm("mul.rn.f32x2 %0, %1, %2;" : "=l"(c) : "l"(a), "l"(b)); return c;
}
__device__ __forceinline__ u64 fma2(u64 a, u64 b, u64 c) {
    u64 d; asm("fma.rn.f32x2 %0, %1, %2, %3;" : "=l"(d) : "l"(a), "l"(b), "l"(c)); return d;
}
__device__ __forceinline__ float ex2(float x) {
    float y; asm("ex2.approx.ftz.f32 %0, %1;" : "=f"(y) : "f"(x)); return y;
}
__device__ __forceinline__ float lg2(float x) {
    float y; asm("lg2.approx.f32 %0, %1;" : "=f"(y) : "f"(x)); return y;
}

// ---------------------------------------------------------------------------
__device__ __forceinline__ float get_scale(int slot) {
    int v = g_max[slot][0];
    #pragma unroll
    for (int k = 1; k < 8; k++) v = max(v, g_max[slot][k]);
    float m = __int_as_float(v);
    return (m > 1.0f) ? __fdividef(1.0f, m) : 1.0f;
}

// warp->block max reduce, one atomicMax per block. All 256 threads must call.
__device__ __forceinline__ void block_max_atomic(float val, int slot) {
    int v = __float_as_int(val);   // valid ordering: all values non-negative
    #pragma unroll
    for (int o = 16; o > 0; o >>= 1) v = max(v, __shfl_xor_sync(0xffffffffu, v, o));
    __shared__ int s_red[8];
    if ((threadIdx.x & 31) == 0) s_red[threadIdx.x >> 5] = v;
    __syncthreads();
    if (threadIdx.x == 0) {
        int m = s_red[0];
        #pragma unroll
        for (int k = 1; k < 8; k++) m = max(m, s_red[k]);
        atomicMax(&g_max[slot][blockIdx.x & 7], m);
    }
}

// ---------------------------------------------------------------------------
// kA: (c,g)-item pairs, f32x2 throughout; one wave of 592 blocks, each warp
// covers a contiguous 3-4 pair range. FIRST: old R read straight from x.
template<bool FIRST>
__global__ void __launch_bounds__(256, 4)
kA(const int* __restrict__ I, const float* __restrict__ x, int slotR, int slotOut) {
    const int tid  = threadIdx.x;
    const int lane = tid & 31;
    const int hf   = lane >> 4;                   // item-of-pair selector
    const int j    = lane & 15;                   // b-pair index
    const int wid  = blockIdx.x * 8 + (tid >> 5); // 0..KA_NW-1

    float sR = FIRST ? 1.0f : get_scale(slotR);
    float s3 = sR * sR * sR;
    float kexp = s3 * KEXP;                       // scale folded into LSE constant
    u64  kexp2 = pk(kexp, kexp);
    float lmax = 0.0f;

    const int p0 = (int)(((long long)wid * NPAIR) / KA_NW);
    const int p1 = (int)(((long long)(wid + 1) * NPAIR) / KA_NW);

    #pragma unroll 1
    for (int P = p0; P < p1; P++) {
        const int item = 2 * P + hf;
        const int4* ip = reinterpret_cast<const int4*>(I) + item * 6;
        int4 a0 = ip[0], a1 = ip[1], a2 = ip[2], a3 = ip[3], a4 = ip[4], a5 = ip[5];
        int idx[24] = { a0.x,a0.y,a0.z,a0.w, a1.x,a1.y,a1.z,a1.w, a2.x,a2.y,a2.z,a2.w,
                        a3.x,a3.y,a3.z,a3.w, a4.x,a4.y,a4.z,a4.w, a5.x,a5.y,a5.z,a5.w };

        u64 b[8];
        #pragma unroll
        for (int s = 0; s < 8; s++) {
            u64 v0, v1, v2;
            if (FIRST) {
                v0 = pk(x[2 * j * NG + idx[3 * s + 0]], x[(2 * j + 1) * NG + idx[3 * s + 0]]);
                v1 = pk(x[2 * j * NG + idx[3 * s + 1]], x[(2 * j + 1) * NG + idx[3 * s + 1]]);
                v2 = pk(x[2 * j * NG + idx[3 * s + 2]], x[(2 * j + 1) * NG + idx[3 * s + 2]]);
            } else {
                v0 = g_Rt2[idx[3 * s + 0] * 16 + j];
                v1 = g_Rt2[idx[3 * s + 1] * 16 + j];
                v2 = g_Rt2[idx[3 * s + 2] * 16 + j];
            }
            b[s] = mul2(mul2(v0, v1), v2);
        }

        float2 c[8];
        #pragma unroll
        for (int s = 0; s < 8; s++) c[s] = unpk(b[s]);
        float mxx = c[0].x, mxy = c[0].y;
        #pragma unroll
        for (int s = 1; s < 8; s++) { mxx = fmaxf(mxx, c[s].x); mxy = fmaxf(mxy, c[s].y); }
        u64 mneg = pk(-mxx * kexp, -mxy * kexp);
        float sx = 0.0f, sy = 0.0f;
        #pragma unroll
        for (int s = 0; s < 8; s++) {
            float2 f = unpk(fma2(b[s], kexp2, mneg));
            sx += ex2(f.x); sy += ex2(f.y);
        }
        float cvx = fmaf(lg2(sx), KLOG, mxx * s3);
        float cvy = fmaf(lg2(sy), KLOG, mxy * s3);
        g_Cv2[item * 16 + j] = pk(cvx, cvy);
        lmax = fmaxf(lmax, fmaxf(cvx, cvy));
    }
    block_max_atomic(lmax, slotOut);
}

// ---------------------------------------------------------------------------
// kB: one g-pair per warp; matvec over c + LSE over m, f32x2.
// grid 128 x 256 (1024 warps == NG/2)
__global__ void __launch_bounds__(256, 4)
kB(const float* __restrict__ W, int slotCv, int slotOut) {
    __shared__ u64 ws2[NM * NC];
    const int tid = threadIdx.x;
    if (tid < NM) {                               // softmax(W) row tid (W tiny)
        float mx = -1e30f;
        #pragma unroll
        for (int cc = 0; cc < NC; cc++) mx = fmaxf(mx, W[tid * NC + cc]);
        float e[NC]; float sum = 0.0f;
        #pragma unroll
        for (int cc = 0; cc < NC; cc++) { e[cc] = ex2((W[tid * NC + cc] - mx) * 1.4426950409f); sum += e[cc]; }
        float inv = __fdividef(1.0f, sum);
        #pragma unroll
        for (int cc = 0; cc < NC; cc++) { float w = e[cc] * inv; ws2[tid * NC + cc] = pk(w, w); }
    }
    float s1 = get_scale(slotCv);
    __syncthreads();

    const int lane = tid & 31;
    const int hf   = lane >> 4;
    const int j    = lane & 15;
    const int g    = 2 * (blockIdx.x * 8 + (tid >> 5)) + hf;

    u64 h[NM];
    #pragma unroll
    for (int m = 0; m < NM; m++) h[m] = 0ull;
    #pragma unroll
    for (int cc = 0; cc < NC; cc++) {
        u64 cvc = g_Cv2[(cc * NG + g) * 16 + j];
        #pragma unroll
        for (int m = 0; m < NM; m++) h[m] = fma2(ws2[m * NC + cc], cvc, h[m]);
    }
    float2 hh[NM];
    #pragma unroll
    for (int m = 0; m < NM; m++) hh[m] = unpk(h[m]);
    float mxx = hh[0].x, mxy = hh[0].y;
    #pragma unroll
    for (int m = 1; m < NM; m++) { mxx = fmaxf(mxx, hh[m].x); mxy = fmaxf(mxy, hh[m].y); }
    float k1 = s1 * KEXP;                         // scale folded into LSE
    u64 k12 = pk(k1, k1), mneg = pk(-mxx * k1, -mxy * k1);
    float sx = 0.0f, sy = 0.0f;
    #pragma unroll
    for (int m = 0; m < NM; m++) {
        float2 f = unpk(fma2(h[m], k12, mneg));
        sx += ex2(f.x); sy += ex2(f.y);
    }
    float hsx = fmaf(lg2(sx), KLOG, mxx * s1);
    float hsy = fmaf(lg2(sy), KLOG, mxy * s1);
    g_Hs2[g * 16 + j] = pk(hsx, hsy);
    block_max_atomic(fmaxf(hsx, hsy), slotOut);
}

// ---------------------------------------------------------------------------
// kC: elementwise 2-way softor merge (both b-halves per thread), R in place.
// grid 128 x 256 (32768 threads == NG*16). FIRST: old R read from x.
template<bool FIRST>
__global__ void __launch_bounds__(256, 4)
kC(const float* __restrict__ x, int slotR, int slotHs, int slotOut) {
    int t = blockIdx.x * blockDim.x + threadIdx.x;
    float sR = FIRST ? 1.0f : get_scale(slotR);
    float s2 = get_scale(slotHs);

    float2 rr;
    if (FIRST) {
        int g = t >> 4, jj = t & 15;              // matches g_Rt2 layout [g*16+jj]
        rr = make_float2(x[2 * jj * NG + g], x[(2 * jj + 1) * NG + g]);
    } else {
        rr = unpk(g_Rt2[t]);
    }
    float2 hv = unpk(g_Hs2[t]);
    float ax = rr.x * sR, ay = rr.y * sR;
    float bx = hv.x * s2, by = hv.y * s2;
    float Mx = fmaxf(ax, bx), mnx = fminf(ax, bx);
    float My = fmaxf(ay, by), mny = fminf(ay, by);
    float rx = fmaf(lg2(1.0f + ex2((mnx - Mx) * KEXP)), KLOG, Mx);
    float ry = fmaf(lg2(1.0f + ex2((mny - My) * KEXP)), KLOG, My);
    g_Rt2[t] = pk(rx, ry);
    block_max_atomic(fmaxf(rx, ry), slotOut);
}

// ---------------------------------------------------------------------------
// kOut: final scale + unpack back to (B, G); coalesced stores. grid 256 x 256
__global__ void __launch_bounds__(256, 4)
kOut(float* __restrict__ out, int slotR) {
    int t = blockIdx.x * blockDim.x + threadIdx.x;   // t = b*NG + g
    float s = get_scale(slotR);
    int b = t >> 11, g = t & (NG - 1);
    float2 v = unpk(g_Rt2[g * 16 + (b >> 1)]);
    out[t] = ((b & 1) ? v.y : v.x) * s;
}

// ---------------------------------------------------------------------------
extern "C" void kernel_launch(void* const* d_in, const int* in_sizes, int n_in,
                              void* d_out, int out_size) {
    const float* x = (const float*)d_in[0];   // (32, 2048) f32
    const float* W = (const float*)d_in[1];   // (16, 16) f32
    const int*   I = (const int*)  d_in[2];   // (16, 2048, 8, 3) i32
    float* out = (float*)d_out;               // (32, 2048) f32

    // iter 0 (reads x directly; slots 0,1,2)
    kA<true>  <<<KA_BLK, 256>>>(I, x, 0, 0);
    kB        <<<128,    256>>>(W, 0, 1);
    kC<true>  <<<128,    256>>>(x, 0, 1, 2);
    // iters 1..4: slots 3i (Cv), 3i+1 (Hs), 3i+2 (R)
    for (int i = 1; i < 5; i++) {
        kA<false><<<KA_BLK, 256>>>(I, x, 3 * i - 1, 3 * i);
        kB        <<<128,   256>>>(W, 3 * i, 3 * i + 1);
        kC<false><<<128,    256>>>(x, 3 * i - 1, 3 * i + 1, 3 * i + 2);
    }
    kOut<<<256, 256>>>(out, 14);
}

// round 14
// speedup vs baseline: 1.7212x; 1.7212x over previous
#include <cuda_runtime.h>

// Problem constants
#define NG 2048   // G
#define NC 16     // C
#define NM 16     // m
// exp(x/gamma) = ex2(x * 100 * log2(e));  gamma*ln(s) = lg2(s) * gamma*ln2
#define KEXP 144.2695040889f
#define KLOG 0.00693147180560f

typedef unsigned long long u64;

// Packed layouts: element [g*16 + j] = (val[b=2j], val[b=2j+1])
__device__ u64   g_Rt2[NG * 16];         // R (un-normalized; scale in g_max)
__device__ u64   g_Cv2[NC * NG * 16];    // Cv_pre
__device__ u64   g_Hs2[NG * 16];         // Hs_pre
__device__ float g_Ws[NM * NC];          // softmax(W)
__device__ int   g_max[16][8];           // banked float-bit maxes (values >= 0)
// slot 3i=Cv max, 3i+1=Hs max, 3i+2=R max (iter i); slot 15 = constant 1.0

// ---- f32x2 helpers (sm_103a packed fp32) ----
__device__ __forceinline__ u64 pk(float x, float y) {
    u64 v; asm("mov.b64 %0, {%1,%2};" : "=l"(v) : "f"(x), "f"(y)); return v;
}
__device__ __forceinline__ float2 unpk(u64 v) {
    float2 r; asm("mov.b64 {%0,%1}, %2;" : "=f"(r.x), "=f"(r.y) : "l"(v)); return r;
}
__device__ __forceinline__ u64 mul2(u64 a, u64 b) {
    u64 c; asm("mul.rn.f32x2 %0, %1, %2;" : "=l"(c) : "l"(a), "l"(b)); return c;
}
__device__ __forceinline__ u64 fma2(u64 a, u64 b, u64 c) {
    u64 d; asm("fma.rn.f32x2 %0, %1, %2, %3;" : "=l"(d) : "l"(a), "l"(b), "l"(c)); return d;
}
__device__ __forceinline__ float ex2(float x) {
    float y; asm("ex2.approx.ftz.f32 %0, %1;" : "=f"(y) : "f"(x)); return y;
}
__device__ __forceinline__ float lg2(float x) {
    float y; asm("lg2.approx.f32 %0, %1;" : "=f"(y) : "f"(x)); return y;
}

// ---------------------------------------------------------------------------
__device__ __forceinline__ float get_scale(int slot) {
    int v = g_max[slot][0];
    #pragma unroll
    for (int k = 1; k < 8; k++) v = max(v, g_max[slot][k]);
    float m = __int_as_float(v);
    return (m > 1.0f) ? __fdividef(1.0f, m) : 1.0f;
}

// warp->block max reduce, one atomicMax per block. All 256 threads must call.
__device__ __forceinline__ void block_max_atomic(float val, int slot) {
    int v = __float_as_int(val);   // valid ordering: all values non-negative
    #pragma unroll
    for (int o = 16; o > 0; o >>= 1) v = max(v, __shfl_xor_sync(0xffffffffu, v, o));
    __shared__ int s_red[8];
    if ((threadIdx.x & 31) == 0) s_red[threadIdx.x >> 5] = v;
    __syncthreads();
    if (threadIdx.x == 0) {
        int m = s_red[0];
        #pragma unroll
        for (int k = 1; k < 8; k++) m = max(m, s_red[k]);
        atomicMax(&g_max[slot][blockIdx.x & 7], m);
    }
}

// ---------------------------------------------------------------------------
// init: pack x -> Rt2, Ws = softmax(W), reset max banks.  grid 128 x 256
__global__ void k_init(const float* __restrict__ x, const float* __restrict__ W) {
    int t = blockIdx.x * blockDim.x + threadIdx.x;   // t = jj*NG + g
    int jj = t >> 11, g = t & (NG - 1);
    g_Rt2[g * 16 + jj] = pk(x[(2 * jj) * NG + g], x[(2 * jj + 1) * NG + g]);

    if (blockIdx.x == 0) {
        if (threadIdx.x < NM) {
            int m = threadIdx.x;
            float mx = -1e30f;
            #pragma unroll
            for (int c = 0; c < NC; c++) mx = fmaxf(mx, W[m * NC + c]);
            float e[NC]; float sum = 0.0f;
            #pragma unroll
            for (int c = 0; c < NC; c++) { e[c] = ex2((W[m * NC + c] - mx) * 1.4426950409f); sum += e[c]; }
            float inv = __fdividef(1.0f, sum);
            #pragma unroll
            for (int c = 0; c < NC; c++) g_Ws[m * NC + c] = e[c] * inv;
        }
        if (threadIdx.x >= 64 && threadIdx.x < 192) {
            int k = threadIdx.x - 64;
            ((int*)g_max)[k] = (k >= 15 * 8) ? __float_as_int(1.0f) : 0;  // slot 15 == 1.0
        }
    }
}

// ---------------------------------------------------------------------------
// kA: FOUR (c,g) items per warp (8 lanes each); lane q covers b-pairs 2q,2q+1
// via 16B ulonglong2 loads. Halves LDG instruction count vs the u64 version.
// grid 1024 x 256: 8192 warps x 4 items = 32768 items == NC*NG  (R12 bug: 512)
__global__ void __launch_bounds__(256, 3)
kA(const int* __restrict__ I, int slotR, int slotOut) {
    const int tid  = threadIdx.x;
    const int lane = tid & 31;
    const int q    = lane & 7;                     // j-pair: j = 2q, 2q+1
    const int qi   = lane >> 3;                    // which of 4 items
    const int item = (blockIdx.x * 8 + (tid >> 5)) * 4 + qi;

    float sR = get_scale(slotR);
    float s3 = sR * sR * sR;
    float kexp = s3 * KEXP;                        // scale folded into LSE constant
    u64  kexp2 = pk(kexp, kexp);

    const int4* ip = reinterpret_cast<const int4*>(I) + item * 6;  // uniform per 8 lanes
    int4 a0 = ip[0], a1 = ip[1], a2 = ip[2], a3 = ip[3], a4 = ip[4], a5 = ip[5];
    int idx[24] = { a0.x,a0.y,a0.z,a0.w, a1.x,a1.y,a1.z,a1.w, a2.x,a2.y,a2.z,a2.w,
                    a3.x,a3.y,a3.z,a3.w, a4.x,a4.y,a4.z,a4.w, a5.x,a5.y,a5.z,a5.w };

    const ulonglong2* Rt = reinterpret_cast<const ulonglong2*>(g_Rt2);
    u64 b0[8], b1[8];                              // bodies for pairs 2q and 2q+1
    #pragma unroll
    for (int s = 0; s < 8; s++) {
        ulonglong2 A = Rt[idx[3 * s + 0] * 8 + q];
        ulonglong2 Bv = Rt[idx[3 * s + 1] * 8 + q];
        ulonglong2 Cv = Rt[idx[3 * s + 2] * 8 + q];
        b0[s] = mul2(mul2(A.x, Bv.x), Cv.x);
        b1[s] = mul2(mul2(A.y, Bv.y), Cv.y);
    }

    float m0x, m0y, m1x, m1y;
    { float2 f0 = unpk(b0[0]), f1 = unpk(b1[0]); m0x = f0.x; m0y = f0.y; m1x = f1.x; m1y = f1.y; }
    #pragma unroll
    for (int s = 1; s < 8; s++) {
        float2 f0 = unpk(b0[s]), f1 = unpk(b1[s]);
        m0x = fmaxf(m0x, f0.x); m0y = fmaxf(m0y, f0.y);
        m1x = fmaxf(m1x, f1.x); m1y = fmaxf(m1y, f1.y);
    }
    u64 mneg0 = pk(-m0x * kexp, -m0y * kexp);
    u64 mneg1 = pk(-m1x * kexp, -m1y * kexp);
    float s0x = 0.0f, s0y = 0.0f, s1x = 0.0f, s1y = 0.0f;
    #pragma unroll
    for (int s = 0; s < 8; s++) {
        float2 f0 = unpk(fma2(b0[s], kexp2, mneg0));
        float2 f1 = unpk(fma2(b1[s], kexp2, mneg1));
        s0x += ex2(f0.x); s0y += ex2(f0.y);
        s1x += ex2(f1.x); s1y += ex2(f1.y);
    }
    float cv0x = fmaf(lg2(s0x), KLOG, m0x * s3);
    float cv0y = fmaf(lg2(s0y), KLOG, m0y * s3);
    float cv1x = fmaf(lg2(s1x), KLOG, m1x * s3);
    float cv1y = fmaf(lg2(s1y), KLOG, m1y * s3);

    ulonglong2 outv; outv.x = pk(cv0x, cv0y); outv.y = pk(cv1x, cv1y);
    reinterpret_cast<ulonglong2*>(g_Cv2)[item * 8 + q] = outv;

    float lmax = fmaxf(fmaxf(cv0x, cv0y), fmaxf(cv1x, cv1y));
    block_max_atomic(lmax, slotOut);
}

// ---------------------------------------------------------------------------
// kB: one g-pair per warp; matvec over c + LSE over m, f32x2.
// grid 128 x 256 (1024 warps == NG/2)   [identical to R8]
__global__ void __launch_bounds__(256, 4)
kB(int slotCv, int slotOut) {
    __shared__ u64 ws2[NM * NC];
    { float w = g_Ws[threadIdx.x]; ws2[threadIdx.x] = pk(w, w); }
    __syncthreads();

    const int tid  = threadIdx.x;
    const int lane = tid & 31;
    const int hf   = lane >> 4;
    const int j    = lane & 15;
    const int g    = 2 * (blockIdx.x * 8 + (tid >> 5)) + hf;

    float s1 = get_scale(slotCv);

    u64 h[NM];
    #pragma unroll
    for (int m = 0; m < NM; m++) h[m] = 0ull;
    #pragma unroll
    for (int c = 0; c < NC; c++) {
        u64 cvc = g_Cv2[(c * NG + g) * 16 + j];
        #pragma unroll
        for (int m = 0; m < NM; m++) h[m] = fma2(ws2[m * NC + c], cvc, h[m]);
    }
    float2 hh[NM];
    #pragma unroll
    for (int m = 0; m < NM; m++) hh[m] = unpk(h[m]);
    float mxx = hh[0].x, mxy = hh[0].y;
    #pragma unroll
    for (int m = 1; m < NM; m++) { mxx = fmaxf(mxx, hh[m].x); mxy = fmaxf(mxy, hh[m].y); }
    float k1 = s1 * KEXP;                         // scale folded into LSE
    u64 k12 = pk(k1, k1), mneg = pk(-mxx * k1, -mxy * k1);
    float sx = 0.0f, sy = 0.0f;
    #pragma unroll
    for (int m = 0; m < NM; m++) {
        u64 t = fma2(h[m], k12, mneg);
        float2 f = unpk(t);
        sx += ex2(f.x); sy += ex2(f.y);
    }
    float hsx = fmaf(lg2(sx), KLOG, mxx * s1);
    float hsy = fmaf(lg2(sy), KLOG, mxy * s1);
    g_Hs2[g * 16 + j] = pk(hsx, hsy);
    block_max_atomic(fmaxf(hsx, hsy), slotOut);
}

// ---------------------------------------------------------------------------
// kC: elementwise 2-way softor merge (both b-halves per thread), R in place.
// grid 128 x 256 (32768 threads == NG*16)   [identical to R8]
__global__ void __launch_bounds__(256, 4)
kC(int slotR, int slotHs, int slotOut) {
    int t = blockIdx.x * blockDim.x + threadIdx.x;
    float sR = get_scale(slotR);
    float s2 = get_scale(slotHs);

    float2 rr = unpk(g_Rt2[t]);
    float2 hv = unpk(g_Hs2[t]);
    float ax = rr.x * sR, ay = rr.y * sR;
    float bx = hv.x * s2, by = hv.y * s2;
    float mxx = fmaxf(ax, bx), mnx = fminf(ax, bx);
    float mxy = fmaxf(ay, by), mny = fminf(ay, by);
    float rx = fmaf(lg2(1.0f + ex2((mnx - mxx) * KEXP)), KLOG, mxx);
    float ry = fmaf(lg2(1.0f + ex2((mny - mxy) * KEXP)), KLOG, mxy);
    g_Rt2[t] = pk(rx, ry);
    block_max_atomic(fmaxf(rx, ry), slotOut);
}

// ---------------------------------------------------------------------------
// output: scale + unpack back to (B, G); coalesced stores.  grid 256 x 256
__global__ void k_out(float* __restrict__ out, int slotR) {
    int t = blockIdx.x * blockDim.x + threadIdx.x;   // t = b*NG + g
    float s = get_scale(slotR);
    int b = t >> 11, g = t & (NG - 1);
    float2 v = unpk(g_Rt2[g * 16 + (b >> 1)]);
    out[t] = ((b & 1) ? v.y : v.x) * s;
}

// ---------------------------------------------------------------------------
extern "C" void kernel_launch(void* const* d_in, const int* in_sizes, int n_in,
                              void* d_out, int out_size) {
    const float* x = (const float*)d_in[0];   // (32, 2048) f32
    const float* W = (const float*)d_in[1];   // (16, 16) f32
    const int*   I = (const int*)  d_in[2];   // (16, 2048, 8, 3) i32
    float* out = (float*)d_out;               // (32, 2048) f32

    k_init<<<128, 256>>>(x, W);

    int slotR = 15;  // constant 1.0 (x used unscaled in iteration 0)
    for (int i = 0; i < 5; i++) {
        kA<<<1024, 256>>>(I, slotR, 3 * i);
        kB<<<128,  256>>>(3 * i, 3 * i + 1);
        kC<<<128,  256>>>(slotR, 3 * i + 1, 3 * i + 2);
        slotR = 3 * i + 2;
    }

    k_out<<<256, 256>>>(out, slotR);
}